// round 1
// baseline (speedup 1.0000x reference)
#include <cuda_runtime.h>
#include <math.h>
#include <stdint.h>

// Problem constants
#define BATCH 2
#define SEQ   1024
#define DMODEL 1024
#define NHEADS 16
#define HDIM  64
#define FFDIM 4096
#define MROWS (BATCH*SEQ)   // 2048

// ---------------- scratch (static device memory; no allocs allowed) ----------
__device__ float g_h   [MROWS*DMODEL];            // 8 MB   LN1 out
__device__ float g_qkv [MROWS*3*DMODEL];          // 24 MB
__device__ float g_scores[(size_t)BATCH*NHEADS*SEQ*SEQ]; // 128 MB
__device__ float g_ctx [MROWS*DMODEL];            // 8 MB
__device__ float g_x2  [MROWS*DMODEL];            // 8 MB
__device__ float g_h2  [MROWS*DMODEL];            // 8 MB
__device__ float g_u   [MROWS*FFDIM];             // 32 MB

// ---------------- helpers ----------------------------------------------------
__device__ __forceinline__ uint32_t f2tf32(float f) {
    uint32_t r;
    asm("cvt.rna.tf32.f32 %0, %1;" : "=r"(r) : "f"(f));
    return r;
}

__device__ __forceinline__ void mma_tf32_16x8x8(float c[4], const uint32_t a[4], const uint32_t b[2]) {
    asm volatile(
        "mma.sync.aligned.m16n8k8.row.col.f32.tf32.tf32.f32 "
        "{%0,%1,%2,%3}, {%4,%5,%6,%7}, {%8,%9}, {%0,%1,%2,%3};"
        : "+f"(c[0]), "+f"(c[1]), "+f"(c[2]), "+f"(c[3])
        : "r"(a[0]), "r"(a[1]), "r"(a[2]), "r"(a[3]),
          "r"(b[0]), "r"(b[1]));
}

__device__ __forceinline__ float block_sum256(float v, float* sh) {
    int lane = threadIdx.x & 31, w = threadIdx.x >> 5;
    #pragma unroll
    for (int o = 16; o; o >>= 1) v += __shfl_xor_sync(0xffffffffu, v, o);
    if (lane == 0) sh[w] = v;
    __syncthreads();
    float r = (threadIdx.x < 8) ? sh[threadIdx.x] : 0.f;
    if (w == 0) {
        #pragma unroll
        for (int o = 4; o; o >>= 1) r += __shfl_xor_sync(0xffffffffu, r, o);
        if (lane == 0) sh[0] = r;
    }
    __syncthreads();
    r = sh[0];
    __syncthreads();
    return r;
}

__device__ __forceinline__ float block_max256(float v, float* sh) {
    int lane = threadIdx.x & 31, w = threadIdx.x >> 5;
    #pragma unroll
    for (int o = 16; o; o >>= 1) v = fmaxf(v, __shfl_xor_sync(0xffffffffu, v, o));
    if (lane == 0) sh[w] = v;
    __syncthreads();
    float r = (threadIdx.x < 8) ? sh[threadIdx.x] : -1e30f;
    if (w == 0) {
        #pragma unroll
        for (int o = 4; o; o >>= 1) r = fmaxf(r, __shfl_xor_sync(0xffffffffu, r, o));
        if (lane == 0) sh[0] = r;
    }
    __syncthreads();
    r = sh[0];
    __syncthreads();
    return r;
}

// ---------------- layernorm: one block (256 thr) per 1024-wide row -----------
__global__ void ln_kernel(const float* __restrict__ x,
                          const float* __restrict__ g,
                          const float* __restrict__ b,
                          float* __restrict__ out) {
    __shared__ float sh[8];
    int row = blockIdx.x;
    const float4* xr = (const float4*)(x + (size_t)row * DMODEL);
    float4* orow = (float4*)(out + (size_t)row * DMODEL);
    int t = threadIdx.x;
    float4 v = xr[t];
    float s  = v.x + v.y + v.z + v.w;
    float sq = v.x*v.x + v.y*v.y + v.z*v.z + v.w*v.w;
    float S  = block_sum256(s, sh);
    float SQ = block_sum256(sq, sh);
    float mean = S * (1.0f / DMODEL);
    float var  = SQ * (1.0f / DMODEL) - mean * mean;
    float rstd = rsqrtf(var + 1e-5f);
    float4 gv = ((const float4*)g)[t];
    float4 bv = ((const float4*)b)[t];
    float4 o;
    o.x = (v.x - mean) * rstd * gv.x + bv.x;
    o.y = (v.y - mean) * rstd * gv.y + bv.y;
    o.z = (v.z - mean) * rstd * gv.z + bv.z;
    o.w = (v.w - mean) * rstd * gv.w + bv.w;
    orow[t] = o;
}

// ---------------- softmax: one block (256 thr) per 1024-wide row -------------
__global__ void softmax_kernel(float* __restrict__ scores) {
    __shared__ float sh[8];
    int row = blockIdx.x;
    float4* p = (float4*)(scores + (size_t)row * SEQ);
    int t = threadIdx.x;
    float4 v = p[t];
    float m = fmaxf(fmaxf(v.x, v.y), fmaxf(v.z, v.w));
    m = block_max256(m, sh);
    float4 e;
    e.x = expf(v.x - m); e.y = expf(v.y - m);
    e.z = expf(v.z - m); e.w = expf(v.w - m);
    float s = e.x + e.y + e.z + e.w;
    s = block_sum256(s, sh);
    float inv = 1.0f / s;
    e.x *= inv; e.y *= inv; e.z *= inv; e.w *= inv;
    p[t] = e;
}

// ---------------- generic batched tf32 GEMM ----------------------------------
// C[M,N] = act( alpha * A[M,K] @ B + bias[N] + biasmat ) + resid
// TRANSB=false: B is KxN row-major (ldb). TRANSB=true: B is NxK row-major (ldb).
// Batch z -> (bb = z/nh, hh = z%nh); per-operand (b,h) strides.
// biasmat/resid share C's layout (ldc + C batch strides).
template<bool TRANSB>
__global__ __launch_bounds__(256)
void gemm_tf32(int Mv, int Nv, int Kv,
               const float* __restrict__ A, int lda, long long sAb, long long sAh,
               const float* __restrict__ Bm, int ldb, long long sBb, long long sBh,
               float* __restrict__ C, int ldc, long long sCb, long long sCh,
               int nh,
               const float* __restrict__ bias, float alpha,
               const float* __restrict__ biasmat,
               const float* __restrict__ resid, int act) {
    __shared__ uint32_t As[128][20];
    __shared__ uint32_t Bs[128][20];

    int z = blockIdx.z;
    int bb = z / nh, hh = z % nh;
    A  += bb * sAb + hh * sAh;
    Bm += bb * sBb + hh * sBh;
    long long coff = bb * sCb + hh * sCh;
    C += coff;
    const float* bmat = biasmat ? biasmat + coff : nullptr;
    const float* rptr = resid ? resid + coff : nullptr;

    int row0 = blockIdx.y * 128, col0 = blockIdx.x * 128;
    int tid = threadIdx.x, lane = tid & 31, warp = tid >> 5;
    int wr = warp >> 2, wc = warp & 3;     // 2x4 warp grid -> 64x32 per warp
    int r = lane >> 2, cq = lane & 3;

    float acc[4][4][4];
    #pragma unroll
    for (int i = 0; i < 4; ++i)
        #pragma unroll
        for (int j = 0; j < 4; ++j)
            #pragma unroll
            for (int e = 0; e < 4; ++e) acc[i][j][e] = 0.f;

    int ktiles = Kv / 16;
    for (int kt = 0; kt < ktiles; ++kt) {
        // A tile: 128 rows x 16 cols, float4 loads
        #pragma unroll
        for (int i = 0; i < 2; ++i) {
            int slot = tid + i * 256;
            int ar = slot >> 2, ac = (slot & 3) * 4;
            float4 v = *(const float4*)(A + (size_t)(row0 + ar) * lda + kt * 16 + ac);
            uint32_t* d = &As[ar][ac];
            d[0] = f2tf32(v.x); d[1] = f2tf32(v.y); d[2] = f2tf32(v.z); d[3] = f2tf32(v.w);
        }
        // B tile into Bs[n][k]
        if (TRANSB) {
            // B is NxK row-major: direct float4 copy
            #pragma unroll
            for (int i = 0; i < 2; ++i) {
                int slot = tid + i * 256;
                int br = slot >> 2, bc = (slot & 3) * 4;
                float4 v = make_float4(0.f, 0.f, 0.f, 0.f);
                if (col0 + br < Nv)
                    v = *(const float4*)(Bm + (size_t)(col0 + br) * ldb + kt * 16 + bc);
                uint32_t* d = &Bs[br][bc];
                d[0] = f2tf32(v.x); d[1] = f2tf32(v.y); d[2] = f2tf32(v.z); d[3] = f2tf32(v.w);
            }
        } else {
            // B is KxN row-major: coalesced scalar loads, transposed store
            #pragma unroll
            for (int i = 0; i < 8; ++i) {
                int slot = tid + i * 256;
                int kr = slot >> 7;          // 0..15
                int n  = slot & 127;         // 0..127
                float v = 0.f;
                if (col0 + n < Nv)
                    v = Bm[(size_t)(kt * 16 + kr) * ldb + col0 + n];
                Bs[n][kr] = f2tf32(v);
            }
        }
        __syncthreads();

        #pragma unroll
        for (int kk = 0; kk < 16; kk += 8) {
            uint32_t af[4][4], bf[4][2];
            #pragma unroll
            for (int mi = 0; mi < 4; ++mi) {
                int m0 = wr * 64 + mi * 16;
                af[mi][0] = As[m0 + r    ][kk + cq    ];
                af[mi][1] = As[m0 + r + 8][kk + cq    ];
                af[mi][2] = As[m0 + r    ][kk + cq + 4];
                af[mi][3] = As[m0 + r + 8][kk + cq + 4];
            }
            #pragma unroll
            for (int ni = 0; ni < 4; ++ni) {
                int n0 = wc * 32 + ni * 8;
                bf[ni][0] = Bs[n0 + r][kk + cq    ];
                bf[ni][1] = Bs[n0 + r][kk + cq + 4];
            }
            #pragma unroll
            for (int mi = 0; mi < 4; ++mi)
                #pragma unroll
                for (int ni = 0; ni < 4; ++ni)
                    mma_tf32_16x8x8(acc[mi][ni], af[mi], bf[ni]);
        }
        __syncthreads();
    }

    // epilogue
    #pragma unroll
    for (int mi = 0; mi < 4; ++mi) {
        #pragma unroll
        for (int ni = 0; ni < 4; ++ni) {
            int rbase = row0 + wr * 64 + mi * 16 + r;
            int cbase = col0 + wc * 32 + ni * 8 + cq * 2;
            #pragma unroll
            for (int e = 0; e < 4; ++e) {
                int rr = rbase + (e >> 1) * 8;
                int cc = cbase + (e & 1);
                if (rr < Mv && cc < Nv) {
                    float v = acc[mi][ni][e] * alpha;
                    if (bias) v += bias[cc];
                    size_t off = (size_t)rr * ldc + cc;
                    if (bmat) v += bmat[off];
                    if (act) { // mish
                        float sp = (v > 20.f) ? v : log1pf(expf(v));
                        v = v * tanhf(sp);
                    }
                    if (rptr) v += rptr[off];
                    C[off] = v;
                }
            }
        }
    }
}

// ---------------- launch -----------------------------------------------------
extern "C" void kernel_launch(void* const* d_in, const int* in_sizes, int n_in,
                              void* d_out, int out_size) {
    (void)in_sizes; (void)n_in; (void)out_size;
    const float* x         = (const float*)d_in[0];
    const float* attn_bias = (const float*)d_in[1];
    const float* ln1_g     = (const float*)d_in[2];
    const float* ln1_b     = (const float*)d_in[3];
    const float* Wqkv      = (const float*)d_in[4];
    const float* bqkv      = (const float*)d_in[5];
    const float* Wo        = (const float*)d_in[6];
    const float* bo        = (const float*)d_in[7];
    const float* ln2_g     = (const float*)d_in[8];
    const float* ln2_b     = (const float*)d_in[9];
    const float* W1        = (const float*)d_in[10];
    const float* b1        = (const float*)d_in[11];
    const float* W2        = (const float*)d_in[12];
    const float* b2        = (const float*)d_in[13];
    float* out = (float*)d_out;

    float *h, *qkv, *scores, *ctx, *x2, *h2, *u;
    cudaGetSymbolAddress((void**)&h,      g_h);
    cudaGetSymbolAddress((void**)&qkv,    g_qkv);
    cudaGetSymbolAddress((void**)&scores, g_scores);
    cudaGetSymbolAddress((void**)&ctx,    g_ctx);
    cudaGetSymbolAddress((void**)&x2,     g_x2);
    cudaGetSymbolAddress((void**)&h2,     g_h2);
    cudaGetSymbolAddress((void**)&u,      g_u);

    const long long SQKV = (long long)SEQ * 3 * DMODEL;   // per-batch stride in qkv
    const long long SSC  = (long long)SEQ * SEQ;          // per-head stride in scores

    // 1) LN1
    ln_kernel<<<MROWS, 256>>>(x, ln1_g, ln1_b, h);

    // 2) QKV = h @ Wqkv + bqkv      (2048 x 3072 x 1024)
    gemm_tf32<false><<<dim3(3 * DMODEL / 128, MROWS / 128, 1), 256>>>(
        MROWS, 3 * DMODEL, DMODEL,
        h, DMODEL, 0, 0,
        Wqkv, 3 * DMODEL, 0, 0,
        qkv, 3 * DMODEL, 0, 0,
        1, bqkv, 1.f, nullptr, nullptr, 0);

    // 3) scores = scale * q @ k^T + attn_bias    per (b,h): 1024x1024x64
    gemm_tf32<true><<<dim3(SEQ / 128, SEQ / 128, BATCH * NHEADS), 256>>>(
        SEQ, SEQ, HDIM,
        qkv,          3 * DMODEL, SQKV, 64,        // q slice
        qkv + DMODEL, 3 * DMODEL, SQKV, 64,        // k slice (N x K row-major)
        scores, SEQ, (long long)NHEADS * SSC, SSC,
        NHEADS, nullptr, 0.125f, attn_bias, nullptr, 0);

    // 4) softmax rows
    softmax_kernel<<<BATCH * NHEADS * SEQ, 256>>>(scores);

    // 5) ctx = attn @ v    per (b,h): 1024x64x1024
    gemm_tf32<false><<<dim3(1, SEQ / 128, BATCH * NHEADS), 256>>>(
        SEQ, HDIM, SEQ,
        scores, SEQ, (long long)NHEADS * SSC, SSC,
        qkv + 2 * DMODEL, 3 * DMODEL, SQKV, 64,    // v slice (K x N row-major)
        ctx, DMODEL, (long long)SEQ * DMODEL, 64,
        NHEADS, nullptr, 1.f, nullptr, nullptr, 0);

    // 6) x2 = x + ctx @ Wo + bo     (2048 x 1024 x 1024)
    gemm_tf32<false><<<dim3(DMODEL / 128, MROWS / 128, 1), 256>>>(
        MROWS, DMODEL, DMODEL,
        ctx, DMODEL, 0, 0,
        Wo, DMODEL, 0, 0,
        x2, DMODEL, 0, 0,
        1, bo, 1.f, nullptr, x, 0);

    // 7) LN2
    ln_kernel<<<MROWS, 256>>>(x2, ln2_g, ln2_b, h2);

    // 8) u = mish(h2 @ W1 + b1)     (2048 x 4096 x 1024)
    gemm_tf32<false><<<dim3(FFDIM / 128, MROWS / 128, 1), 256>>>(
        MROWS, FFDIM, DMODEL,
        h2, DMODEL, 0, 0,
        W1, FFDIM, 0, 0,
        u, FFDIM, 0, 0,
        1, b1, 1.f, nullptr, nullptr, 1);

    // 9) out = x2 + u @ W2 + b2     (2048 x 1024 x 4096)
    gemm_tf32<false><<<dim3(DMODEL / 128, MROWS / 128, 1), 256>>>(
        MROWS, DMODEL, FFDIM,
        u, FFDIM, 0, 0,
        W2, DMODEL, 0, 0,
        out, DMODEL, 0, 0,
        1, b2, 1.f, nullptr, x2, 0);
}

// round 4
// speedup vs baseline: 1.9354x; 1.9354x over previous
#include <cuda_runtime.h>
#include <math.h>
#include <stdint.h>

// Problem constants
#define BATCH 2
#define SEQ   1024
#define DMODEL 1024
#define NHEADS 16
#define HDIM  64
#define FFDIM 4096
#define MROWS (BATCH*SEQ)   // 2048

// ---------------- scratch (static device memory; no allocs allowed) ----------
__device__ float g_h   [MROWS*DMODEL];            // LN1 out
__device__ float g_qkv [MROWS*3*DMODEL];          // QKV
__device__ float g_ctx [MROWS*DMODEL];            // attention out
__device__ float g_x2  [MROWS*DMODEL];            // residual 1 out
__device__ float g_h2  [MROWS*DMODEL];            // LN2 out
__device__ float g_u   [(size_t)MROWS*FFDIM];     // FFN hidden

// ---------------- helpers ----------------------------------------------------
__device__ __forceinline__ uint32_t f2tf32(float f) {
    uint32_t r;
    asm("cvt.rna.tf32.f32 %0, %1;" : "=r"(r) : "f"(f));
    return r;
}

__device__ __forceinline__ void mma_tf32_16x8x8(float c[4], const uint32_t a[4], const uint32_t b[2]) {
    asm volatile(
        "mma.sync.aligned.m16n8k8.row.col.f32.tf32.tf32.f32 "
        "{%0,%1,%2,%3}, {%4,%5,%6,%7}, {%8,%9}, {%0,%1,%2,%3};"
        : "+f"(c[0]), "+f"(c[1]), "+f"(c[2]), "+f"(c[3])
        : "r"(a[0]), "r"(a[1]), "r"(a[2]), "r"(a[3]),
          "r"(b[0]), "r"(b[1]));
}

__device__ __forceinline__ void cp16(void* smem_dst, const void* gsrc) {
    uint32_t s = (uint32_t)__cvta_generic_to_shared(smem_dst);
    asm volatile("cp.async.cg.shared.global [%0], [%1], 16;" :: "r"(s), "l"(gsrc));
}
#define CP_COMMIT() asm volatile("cp.async.commit_group;")

__device__ __forceinline__ float block_sum256(float v, float* sh) {
    int lane = threadIdx.x & 31, w = threadIdx.x >> 5;
    #pragma unroll
    for (int o = 16; o; o >>= 1) v += __shfl_xor_sync(0xffffffffu, v, o);
    if (lane == 0) sh[w] = v;
    __syncthreads();
    float r = (threadIdx.x < 8) ? sh[threadIdx.x] : 0.f;
    if (w == 0) {
        #pragma unroll
        for (int o = 4; o; o >>= 1) r += __shfl_xor_sync(0xffffffffu, r, o);
        if (lane == 0) sh[0] = r;
    }
    __syncthreads();
    r = sh[0];
    __syncthreads();
    return r;
}

// ---------------- layernorm: one block (256 thr) per 1024-wide row -----------
__global__ void ln_kernel(const float* __restrict__ x,
                          const float* __restrict__ g,
                          const float* __restrict__ b,
                          float* __restrict__ out) {
    __shared__ float sh[8];
    int row = blockIdx.x;
    const float4* xr = (const float4*)(x + (size_t)row * DMODEL);
    float4* orow = (float4*)(out + (size_t)row * DMODEL);
    int t = threadIdx.x;
    float4 v = xr[t];
    float s  = v.x + v.y + v.z + v.w;
    float sq = v.x*v.x + v.y*v.y + v.z*v.z + v.w*v.w;
    float S  = block_sum256(s, sh);
    float SQ = block_sum256(sq, sh);
    float mean = S * (1.0f / DMODEL);
    float var  = SQ * (1.0f / DMODEL) - mean * mean;
    float rstd = rsqrtf(var + 1e-5f);
    float4 gv = ((const float4*)g)[t];
    float4 bv = ((const float4*)b)[t];
    float4 o;
    o.x = (v.x - mean) * rstd * gv.x + bv.x;
    o.y = (v.y - mean) * rstd * gv.y + bv.y;
    o.z = (v.z - mean) * rstd * gv.z + bv.z;
    o.w = (v.w - mean) * rstd * gv.w + bv.w;
    orow[t] = o;
}

// ---------------- fused flash attention --------------------------------------
// One block: (b, h, 128 q-rows). Loop over 16 key-tiles of 64.
// 8 warps, each owns 16 q-rows x FULL 64 key-cols -> softmax is warp-local.
// S = scale*Q@K^T + bias ; online softmax ; O += P@V ; final O/l -> ctx.
#define APITCH 68
#define ATTN_SMEM_WORDS (128*APITCH + 64*APITCH + 64*APITCH + 128*APITCH)
#define ATTN_SMEM_BYTES (ATTN_SMEM_WORDS*4)

__global__ __launch_bounds__(256, 2)
void attn_kernel(const float* __restrict__ qkv,
                 const float* __restrict__ bias,
                 float* __restrict__ ctx) {
    extern __shared__ uint32_t sm[];
    uint32_t (*Qs)[APITCH] = (uint32_t(*)[APITCH])(sm);
    uint32_t (*Ks)[APITCH] = (uint32_t(*)[APITCH])(sm + 128*APITCH);
    uint32_t (*Vs)[APITCH] = (uint32_t(*)[APITCH])(sm + 128*APITCH + 64*APITCH);
    uint32_t (*Ps)[APITCH] = (uint32_t(*)[APITCH])(sm + 128*APITCH + 128*APITCH);

    int q0 = blockIdx.x * 128;
    int h  = blockIdx.y;
    int b  = blockIdx.z;
    int tid = threadIdx.x, lane = tid & 31, warp = tid >> 5;
    int r = lane >> 2, cq = lane & 3;
    int m0 = warp * 16;                 // warp owns rows m0..m0+15

    const size_t rowstride = 3 * DMODEL;
    const float* qbase  = qkv + (size_t)(b*SEQ + q0) * rowstride + h*HDIM;
    const float* kslice = qkv + DMODEL   + h*HDIM + (size_t)(b*SEQ) * rowstride;
    const float* vslice = qkv + 2*DMODEL + h*HDIM + (size_t)(b*SEQ) * rowstride;
    const float* bias_bh = bias + ((size_t)(b*NHEADS + h)) * SEQ * SEQ;

    // Q tile load (128x64), convert to tf32
    #pragma unroll
    for (int i = 0; i < 8; ++i) {
        int slot = tid + i * 256;            // 0..2047
        int qr = slot >> 4, qc = (slot & 15) * 4;
        float4 v = *(const float4*)(qbase + (size_t)qr * rowstride + qc);
        Qs[qr][qc+0] = f2tf32(v.x); Qs[qr][qc+1] = f2tf32(v.y);
        Qs[qr][qc+2] = f2tf32(v.z); Qs[qr][qc+3] = f2tf32(v.w);
    }

    float oacc[8][4];                    // 16 rows x 64 dims
    #pragma unroll
    for (int ni = 0; ni < 8; ++ni)
        #pragma unroll
        for (int e = 0; e < 4; ++e) oacc[ni][e] = 0.f;
    float m_run[2] = {-1e30f, -1e30f};   // rows r, r+8
    float l_run[2] = {0.f, 0.f};

    for (int t = 0; t < SEQ/64; ++t) {
        __syncthreads();   // all warps done reading Ks/Vs from prev tile
        const float* kb = kslice + (size_t)(t*64) * rowstride;
        const float* vb = vslice + (size_t)(t*64) * rowstride;
        #pragma unroll
        for (int i = 0; i < 4; ++i) {
            int slot = tid + i * 256;        // 0..1023
            int kr = slot >> 4, kc = (slot & 15) * 4;
            float4 kv = *(const float4*)(kb + (size_t)kr * rowstride + kc);
            float4 vv = *(const float4*)(vb + (size_t)kr * rowstride + kc);
            Ks[kr][kc+0] = f2tf32(kv.x); Ks[kr][kc+1] = f2tf32(kv.y);
            Ks[kr][kc+2] = f2tf32(kv.z); Ks[kr][kc+3] = f2tf32(kv.w);
            Vs[kr][kc+0] = f2tf32(vv.x); Vs[kr][kc+1] = f2tf32(vv.y);
            Vs[kr][kc+2] = f2tf32(vv.z); Vs[kr][kc+3] = f2tf32(vv.w);
        }
        __syncthreads();

        // ---- S = Q @ K^T (16 rows x 64 cols x K64) ----
        float sacc[8][4];
        #pragma unroll
        for (int ni = 0; ni < 8; ++ni)
            #pragma unroll
            for (int e = 0; e < 4; ++e) sacc[ni][e] = 0.f;

        #pragma unroll
        for (int kk = 0; kk < 64; kk += 8) {
            uint32_t af[4], bf[8][2];
            af[0] = Qs[m0 + r    ][kk + cq    ];
            af[1] = Qs[m0 + r + 8][kk + cq    ];
            af[2] = Qs[m0 + r    ][kk + cq + 4];
            af[3] = Qs[m0 + r + 8][kk + cq + 4];
            #pragma unroll
            for (int ni = 0; ni < 8; ++ni) {
                bf[ni][0] = Ks[ni*8 + r][kk + cq    ];
                bf[ni][1] = Ks[ni*8 + r][kk + cq + 4];
            }
            #pragma unroll
            for (int ni = 0; ni < 8; ++ni)
                mma_tf32_16x8x8(sacc[ni], af, bf[ni]);
        }

        // ---- scale + bias + online softmax (warp-local, full row) ----
        #pragma unroll
        for (int e2 = 0; e2 < 2; ++e2) {
            int lr = m0 + r + e2*8;
            const float* brow = bias_bh + (size_t)(q0 + lr) * SEQ + t*64;
            float sv[16];
            #pragma unroll
            for (int ni = 0; ni < 8; ++ni) {
                float2 bb = __ldg((const float2*)(brow + ni*8 + 2*cq));
                sv[ni*2    ] = sacc[ni][e2*2    ] * 0.125f + bb.x;
                sv[ni*2 + 1] = sacc[ni][e2*2 + 1] * 0.125f + bb.y;
            }
            float mx = sv[0];
            #pragma unroll
            for (int j = 1; j < 16; ++j) mx = fmaxf(mx, sv[j]);
            mx = fmaxf(mx, __shfl_xor_sync(0xffffffffu, mx, 1));
            mx = fmaxf(mx, __shfl_xor_sync(0xffffffffu, mx, 2));
            float mnew = fmaxf(m_run[e2], mx);
            float corr = __expf(m_run[e2] - mnew);
            float rs = 0.f;
            #pragma unroll
            for (int j = 0; j < 16; ++j) { sv[j] = __expf(sv[j] - mnew); rs += sv[j]; }
            rs += __shfl_xor_sync(0xffffffffu, rs, 1);
            rs += __shfl_xor_sync(0xffffffffu, rs, 2);
            l_run[e2] = l_run[e2] * corr + rs;
            m_run[e2] = mnew;
            #pragma unroll
            for (int ni = 0; ni < 8; ++ni) {
                oacc[ni][e2*2    ] *= corr;
                oacc[ni][e2*2 + 1] *= corr;
                Ps[lr][ni*8 + 2*cq    ] = f2tf32(sv[ni*2    ]);
                Ps[lr][ni*8 + 2*cq + 1] = f2tf32(sv[ni*2 + 1]);
            }
        }
        __syncwarp();   // Ps rows are warp-private: warp-level visibility suffices

        // ---- O += P @ V (16 rows x 64 dims x K64 keys) ----
        #pragma unroll
        for (int kk = 0; kk < 64; kk += 8) {
            uint32_t af[4], bf[8][2];
            af[0] = Ps[m0 + r    ][kk + cq    ];
            af[1] = Ps[m0 + r + 8][kk + cq    ];
            af[2] = Ps[m0 + r    ][kk + cq + 4];
            af[3] = Ps[m0 + r + 8][kk + cq + 4];
            #pragma unroll
            for (int ni = 0; ni < 8; ++ni) {
                bf[ni][0] = Vs[kk + cq    ][ni*8 + r];
                bf[ni][1] = Vs[kk + cq + 4][ni*8 + r];
            }
            #pragma unroll
            for (int ni = 0; ni < 8; ++ni)
                mma_tf32_16x8x8(oacc[ni], af, bf[ni]);
        }
    }

    // ---- epilogue: O / l -> ctx[b, q, h*64 + d] ----
    #pragma unroll
    for (int e2 = 0; e2 < 2; ++e2) {
        float inv = 1.0f / l_run[e2];
        int lr = m0 + r + e2*8;
        float* crow = ctx + (size_t)(b*SEQ + q0 + lr) * DMODEL + h*HDIM;
        #pragma unroll
        for (int ni = 0; ni < 8; ++ni) {
            float2 o;
            o.x = oacc[ni][e2*2    ] * inv;
            o.y = oacc[ni][e2*2 + 1] * inv;
            *(float2*)(crow + ni*8 + 2*cq) = o;
        }
    }
}

// ---------------- tf32 GEMM, cp.async double-buffered, group-swizzled --------
// C[M,N] = act( A[M,K] @ B[K,N] + bias[N] ) + resid
// All of M,N multiples of 128; K multiple of 16.
__global__ __launch_bounds__(256, 2)
void gemm_tf32(int Mv, int Nv, int Kv,
               const float* __restrict__ A, int lda,
               const float* __restrict__ B, int ldb,
               float* __restrict__ C, int ldc,
               const float* __restrict__ bias,
               const float* __restrict__ resid, int act) {
    __shared__ float As[2][128][20];
    __shared__ float Bs[2][16][132];

    // group-of-8 swizzle for L2 reuse
    int gx = gridDim.x, gy = gridDim.y;
    int pid = blockIdx.y * gx + blockIdx.x;
    const int GRP = 8;
    int width = GRP * gx;
    int gid = pid / width;
    int first = gid * GRP;
    int gsz = min(gy - first, GRP);
    int pid_m = first + (pid % gsz);
    int pid_n = (pid % width) / gsz;
    int row0 = pid_m * 128, col0 = pid_n * 128;

    int tid = threadIdx.x, lane = tid & 31, warp = tid >> 5;
    int wr = warp >> 2, wc = warp & 3;     // 2x4 grid -> 64x32 per warp
    int r = lane >> 2, cq = lane & 3;

    float acc[4][4][4];
    #pragma unroll
    for (int i = 0; i < 4; ++i)
        #pragma unroll
        for (int j = 0; j < 4; ++j)
            #pragma unroll
            for (int e = 0; e < 4; ++e) acc[i][j][e] = 0.f;

    int ktiles = Kv / 16;

    auto load_tile = [&](int kt, int buf) {
        #pragma unroll
        for (int i = 0; i < 2; ++i) {
            int slot = tid + i * 256;
            int ar = slot >> 2, ac = (slot & 3) * 4;
            cp16(&As[buf][ar][ac], A + (size_t)(row0 + ar) * lda + kt * 16 + ac);
        }
        #pragma unroll
        for (int i = 0; i < 2; ++i) {
            int slot = tid + i * 256;
            int kr = slot >> 5, nc = (slot & 31) * 4;
            cp16(&Bs[buf][kr][nc], B + (size_t)(kt * 16 + kr) * ldb + col0 + nc);
        }
        CP_COMMIT();
    };

    load_tile(0, 0);
    for (int kt = 0; kt < ktiles; ++kt) {
        int buf = kt & 1;
        if (kt + 1 < ktiles) {
            load_tile(kt + 1, buf ^ 1);
            asm volatile("cp.async.wait_group 1;");
        } else {
            asm volatile("cp.async.wait_group 0;");
        }
        __syncthreads();

        #pragma unroll
        for (int kk = 0; kk < 16; kk += 8) {
            uint32_t af[4][4], bf[4][2];
            #pragma unroll
            for (int mi = 0; mi < 4; ++mi) {
                int mm = wr * 64 + mi * 16;
                af[mi][0] = f2tf32(As[buf][mm + r    ][kk + cq    ]);
                af[mi][1] = f2tf32(As[buf][mm + r + 8][kk + cq    ]);
                af[mi][2] = f2tf32(As[buf][mm + r    ][kk + cq + 4]);
                af[mi][3] = f2tf32(As[buf][mm + r + 8][kk + cq + 4]);
            }
            #pragma unroll
            for (int ni = 0; ni < 4; ++ni) {
                int nn = wc * 32 + ni * 8;
                bf[ni][0] = f2tf32(Bs[buf][kk + cq    ][nn + r]);
                bf[ni][1] = f2tf32(Bs[buf][kk + cq + 4][nn + r]);
            }
            #pragma unroll
            for (int mi = 0; mi < 4; ++mi)
                #pragma unroll
                for (int ni = 0; ni < 4; ++ni)
                    mma_tf32_16x8x8(acc[mi][ni], af[mi], bf[ni]);
        }
        __syncthreads();
    }

    // epilogue: bias -> act -> resid -> store (float2)
    #pragma unroll
    for (int mi = 0; mi < 4; ++mi) {
        int rb = row0 + wr * 64 + mi * 16 + r;
        #pragma unroll
        for (int ni = 0; ni < 4; ++ni) {
            int cb = col0 + wc * 32 + ni * 8 + 2 * cq;
            float2 bb = make_float2(0.f, 0.f);
            if (bias) bb = *(const float2*)(bias + cb);
            #pragma unroll
            for (int e2 = 0; e2 < 2; ++e2) {
                int rr = rb + e2 * 8;
                float v0 = acc[mi][ni][e2*2    ] + bb.x;
                float v1 = acc[mi][ni][e2*2 + 1] + bb.y;
                if (act) {
                    float sp0 = (v0 > 20.f) ? v0 : log1pf(expf(v0));
                    float sp1 = (v1 > 20.f) ? v1 : log1pf(expf(v1));
                    v0 = v0 * tanhf(sp0);
                    v1 = v1 * tanhf(sp1);
                }
                size_t off = (size_t)rr * ldc + cb;
                if (resid) {
                    float2 rv = *(const float2*)(resid + off);
                    v0 += rv.x; v1 += rv.y;
                }
                *(float2*)(C + off) = make_float2(v0, v1);
            }
        }
    }
}

// ---------------- launch -----------------------------------------------------
extern "C" void kernel_launch(void* const* d_in, const int* in_sizes, int n_in,
                              void* d_out, int out_size) {
    (void)in_sizes; (void)n_in; (void)out_size;
    const float* x         = (const float*)d_in[0];
    const float* attn_bias = (const float*)d_in[1];
    const float* ln1_g     = (const float*)d_in[2];
    const float* ln1_b     = (const float*)d_in[3];
    const float* Wqkv      = (const float*)d_in[4];
    const float* bqkv      = (const float*)d_in[5];
    const float* Wo        = (const float*)d_in[6];
    const float* bo        = (const float*)d_in[7];
    const float* ln2_g     = (const float*)d_in[8];
    const float* ln2_b     = (const float*)d_in[9];
    const float* W1        = (const float*)d_in[10];
    const float* b1        = (const float*)d_in[11];
    const float* W2        = (const float*)d_in[12];
    const float* b2        = (const float*)d_in[13];
    float* out = (float*)d_out;

    float *h, *qkv, *ctx, *x2, *h2, *u;
    cudaGetSymbolAddress((void**)&h,   g_h);
    cudaGetSymbolAddress((void**)&qkv, g_qkv);
    cudaGetSymbolAddress((void**)&ctx, g_ctx);
    cudaGetSymbolAddress((void**)&x2,  g_x2);
    cudaGetSymbolAddress((void**)&h2,  g_h2);
    cudaGetSymbolAddress((void**)&u,   g_u);

    cudaFuncSetAttribute(attn_kernel,
                         cudaFuncAttributeMaxDynamicSharedMemorySize,
                         ATTN_SMEM_BYTES);

    // 1) LN1
    ln_kernel<<<MROWS, 256>>>(x, ln1_g, ln1_b, h);

    // 2) QKV = h @ Wqkv + bqkv      (2048 x 3072 x 1024)
    gemm_tf32<<<dim3(3 * DMODEL / 128, MROWS / 128), 256>>>(
        MROWS, 3 * DMODEL, DMODEL,
        h, DMODEL, Wqkv, 3 * DMODEL, qkv, 3 * DMODEL,
        bqkv, nullptr, 0);

    // 3-5) fused flash attention -> ctx
    attn_kernel<<<dim3(SEQ / 128, NHEADS, BATCH), 256, ATTN_SMEM_BYTES>>>(
        qkv, attn_bias, ctx);

    // 6) x2 = x + ctx @ Wo + bo     (2048 x 1024 x 1024)
    gemm_tf32<<<dim3(DMODEL / 128, MROWS / 128), 256>>>(
        MROWS, DMODEL, DMODEL,
        ctx, DMODEL, Wo, DMODEL, x2, DMODEL,
        bo, x, 0);

    // 7) LN2
    ln_kernel<<<MROWS, 256>>>(x2, ln2_g, ln2_b, h2);

    // 8) u = mish(h2 @ W1 + b1)     (2048 x 4096 x 1024)
    gemm_tf32<<<dim3(FFDIM / 128, MROWS / 128), 256>>>(
        MROWS, FFDIM, DMODEL,
        h2, DMODEL, W1, FFDIM, u, FFDIM,
        b1, nullptr, 1);

    // 9) out = x2 + u @ W2 + b2     (2048 x 1024 x 4096)
    gemm_tf32<<<dim3(DMODEL / 128, MROWS / 128), 256>>>(
        MROWS, DMODEL, FFDIM,
        u, FFDIM, W2, DMODEL, out, DMODEL,
        b2, x2, 0);
}